// round 1
// baseline (speedup 1.0000x reference)
#include <cuda_runtime.h>
#include <math.h>

#define SEQ 2048
#define DIM 1024
#define NHEADS 8
#define HD 128
#define BM 64
#define BN 64
#define PQ 66   // pad for transposed Q/K tiles [HD][PQ]
#define PV 132  // pad for V tile [BN][PV]
#define PP 68   // pad for P tile [BM][PP]
#define LOG2E 1.4426950408889634f
#define INV_TAU 0.088388347648318447f  /* 1/sqrt(128) */

// ---------------- scratch (device globals; no allocation) ----------------
__device__ float g_itilde[NHEADS * SEQ];
__device__ float g_logsig[NHEADS * SEQ];
__device__ float g_a2[NHEADS * SEQ];      // a_j * log2(e)
__device__ float g_M2[NHEADS * SEQ];      // M_i * log2(e)
__device__ float g_nfloor[NHEADS * SEQ];  // exp(-(csum_i + M_i))

// ---------------- kernel A: gate projections ----------------
// grid = SEQ blocks of 256 threads; warp w handles head w of token blockIdx.x
__global__ void gates_kernel(const float* __restrict__ q, const float* __restrict__ k,
                             const float* __restrict__ v,
                             const float* __restrict__ Wi_w, const float* __restrict__ Wi_b,
                             const float* __restrict__ Wf_w, const float* __restrict__ Wf_b) {
    const int s = blockIdx.x;
    const int h = threadIdx.x >> 5;
    const int lane = threadIdx.x & 31;
    const float* wi = Wi_w + h * 3 * DIM;
    const float* wf = Wf_w + h * 3 * DIM;
    const float* qr = q + (size_t)s * DIM;
    const float* kr = k + (size_t)s * DIM;
    const float* vr = v + (size_t)s * DIM;

    float si = 0.f, sf = 0.f;
#pragma unroll
    for (int m = 0; m < 8; m++) {
        const int d = m * 128 + lane * 4;
        const float4 xq = *reinterpret_cast<const float4*>(qr + d);
        const float4 xk = *reinterpret_cast<const float4*>(kr + d);
        const float4 xv = *reinterpret_cast<const float4*>(vr + d);

        float4 w0 = *reinterpret_cast<const float4*>(wi + d);
        float4 w1 = *reinterpret_cast<const float4*>(wi + DIM + d);
        float4 w2 = *reinterpret_cast<const float4*>(wi + 2 * DIM + d);
        si += xq.x * w0.x + xq.y * w0.y + xq.z * w0.z + xq.w * w0.w;
        si += xk.x * w1.x + xk.y * w1.y + xk.z * w1.z + xk.w * w1.w;
        si += xv.x * w2.x + xv.y * w2.y + xv.z * w2.z + xv.w * w2.w;

        w0 = *reinterpret_cast<const float4*>(wf + d);
        w1 = *reinterpret_cast<const float4*>(wf + DIM + d);
        w2 = *reinterpret_cast<const float4*>(wf + 2 * DIM + d);
        sf += xq.x * w0.x + xq.y * w0.y + xq.z * w0.z + xq.w * w0.w;
        sf += xk.x * w1.x + xk.y * w1.y + xk.z * w1.z + xk.w * w1.w;
        sf += xv.x * w2.x + xv.y * w2.y + xv.z * w2.z + xv.w * w2.w;
    }
#pragma unroll
    for (int o = 16; o; o >>= 1) {
        si += __shfl_xor_sync(0xffffffffu, si, o);
        sf += __shfl_xor_sync(0xffffffffu, sf, o);
    }
    if (lane == 0) {
        g_itilde[h * SEQ + s] = si + Wi_b[h];
        const float ft = sf + Wf_b[h];
        // log_sigmoid(x) = min(x,0) - log1p(exp(-|x|))
        g_logsig[h * SEQ + s] = fminf(ft, 0.f) - log1pf(__expf(-fabsf(ft)));
    }
}

// ---------------- kernel B: per-head prefix sum + prefix max ----------------
// grid = NHEADS blocks of 256 threads, 8 tokens per thread
__global__ void scan_kernel() {
    const int h = blockIdx.x;
    const int t = threadIdx.x;
    __shared__ float sc[256];

    float cs[8];
    float run = 0.f;
#pragma unroll
    for (int m = 0; m < 8; m++) {
        run += g_logsig[h * SEQ + t * 8 + m];
        cs[m] = run;
    }
    sc[t] = run;
    __syncthreads();
#pragma unroll
    for (int off = 1; off < 256; off <<= 1) {
        const float vv = sc[t];
        const float uu = (t >= off) ? sc[t - off] : 0.f;
        __syncthreads();
        sc[t] = vv + uu;
        __syncthreads();
    }
    const float base = (t == 0) ? 0.f : sc[t - 1];

    float a[8], amax[8], csum[8];
    float runm = -3.402823466e38f;
#pragma unroll
    for (int m = 0; m < 8; m++) {
        csum[m] = base + cs[m];
        a[m] = g_itilde[h * SEQ + t * 8 + m] - csum[m];
        runm = fmaxf(runm, a[m]);
        amax[m] = runm;
    }
    __syncthreads();
    sc[t] = runm;
    __syncthreads();
#pragma unroll
    for (int off = 1; off < 256; off <<= 1) {
        const float vv = sc[t];
        const float uu = (t >= off) ? sc[t - off] : -3.402823466e38f;
        __syncthreads();
        sc[t] = fmaxf(vv, uu);
        __syncthreads();
    }
    const float mbase = (t == 0) ? -3.402823466e38f : sc[t - 1];

#pragma unroll
    for (int m = 0; m < 8; m++) {
        const int j = h * SEQ + t * 8 + m;
        const float Mv = fmaxf(mbase, amax[m]);
        g_a2[j] = a[m] * LOG2E;
        g_M2[j] = Mv * LOG2E;
        g_nfloor[j] = exp2f(-(csum[m] + Mv) * LOG2E);
    }
}

// ---------------- kernel C: triangular dual-GEMM (flash mLSTM) ----------------
struct SmemC {
    float Qt[HD][PQ];  // transposed Q tile (scaled by 1/tau)
    float Kt[HD][PQ];  // transposed K tile
    float Vs[BN][PV];  // natural V tile
    float Ps[BM][PP];  // weighted scores
    float a2[BN];
    float M2[BM];
    float nfl[BM];
    float bs[BM];
};

__global__ void __launch_bounds__(256) mlstm_main(const float* __restrict__ q,
                                                  const float* __restrict__ k,
                                                  const float* __restrict__ v,
                                                  float* __restrict__ out) {
    extern __shared__ char smraw[];
    SmemC& sm = *reinterpret_cast<SmemC*>(smraw);

    const int h = blockIdx.y;
    const int p = blockIdx.x;  // 0..15, handles row tiles p and 31-p
    const int tid = threadIdx.x;
    const int lane = tid & 31;
    const int warp = tid >> 5;
    const int tx = tid & 15;
    const int ty = tid >> 4;

    for (int half = 0; half < 2; half++) {
        const int rt = half ? (31 - p) : p;
        const int i0 = rt * BM;

        // stage Q tile transposed (conflict-free: lanes span consecutive dd)
        for (int rr = warp; rr < BM; rr += 8) {
            const float* qrow = q + (size_t)(i0 + rr) * DIM + h * HD;
#pragma unroll
            for (int m = 0; m < 4; m++) {
                const int dd = m * 32 + lane;
                sm.Qt[dd][rr] = qrow[dd] * INV_TAU;
            }
        }
        if (tid < BM) {
            sm.M2[tid] = g_M2[h * SEQ + i0 + tid];
            sm.nfl[tid] = g_nfloor[h * SEQ + i0 + tid];
        }

        float acc[4][8];
#pragma unroll
        for (int r = 0; r < 4; r++)
#pragma unroll
            for (int c = 0; c < 8; c++) acc[r][c] = 0.f;
        float bsum[4] = {0.f, 0.f, 0.f, 0.f};

        for (int ct = 0; ct <= rt; ct++) {
            const int j0 = ct * BN;
            __syncthreads();  // previous iteration's reads of Kt/Vs/Ps done

            // stage K (transposed) and V (natural)
            for (int rr = warp; rr < BN; rr += 8) {
                const float* krow = k + (size_t)(j0 + rr) * DIM + h * HD;
#pragma unroll
                for (int m = 0; m < 4; m++) {
                    const int dd = m * 32 + lane;
                    sm.Kt[dd][rr] = krow[dd];
                }
                const float* vrow = v + (size_t)(j0 + rr) * DIM + h * HD;
                *reinterpret_cast<float4*>(&sm.Vs[rr][lane * 4]) =
                    *reinterpret_cast<const float4*>(vrow + lane * 4);
            }
            if (tid < BN) sm.a2[tid] = g_a2[h * SEQ + j0 + tid];
            __syncthreads();

            // ---- GEMM1: S = (Q/tau) K^T  (4x4 micro-tile, strided mapping) ----
            float sfr[4][4];
#pragma unroll
            for (int r = 0; r < 4; r++)
#pragma unroll
                for (int c = 0; c < 4; c++) sfr[r][c] = 0.f;

#pragma unroll 8
            for (int kk = 0; kk < HD; kk++) {
                const float2 q0 = *reinterpret_cast<const float2*>(&sm.Qt[kk][2 * ty]);
                const float2 q1 = *reinterpret_cast<const float2*>(&sm.Qt[kk][2 * ty + 32]);
                const float2 k0 = *reinterpret_cast<const float2*>(&sm.Kt[kk][2 * tx]);
                const float2 k1 = *reinterpret_cast<const float2*>(&sm.Kt[kk][2 * tx + 32]);
                const float qf[4] = {q0.x, q0.y, q1.x, q1.y};
                const float kf[4] = {k0.x, k0.y, k1.x, k1.y};
#pragma unroll
                for (int r = 0; r < 4; r++)
#pragma unroll
                    for (int c = 0; c < 4; c++) sfr[r][c] += qf[r] * kf[c];
            }

            // ---- decay weights + causal mask + row-sum ----
            const bool diag = (ct == rt);
#pragma unroll
            for (int r = 0; r < 4; r++) {
                const int row = 2 * ty + (r & 1) + 32 * (r >> 1);
                const float m2 = sm.M2[row];
#pragma unroll
                for (int c = 0; c < 4; c++) {
                    const int col = 2 * tx + (c & 1) + 32 * (c >> 1);
                    float w = exp2f(sm.a2[col] - m2);
                    if (diag && (j0 + col > i0 + row)) w = 0.f;
                    sfr[r][c] *= w;
                }
            }
            // row-sum reduction across the 16 tx lanes (stays inside half-warp)
#pragma unroll
            for (int r = 0; r < 4; r++) {
                float rs = sfr[r][0] + sfr[r][1] + sfr[r][2] + sfr[r][3];
#pragma unroll
                for (int o = 8; o; o >>= 1) rs += __shfl_xor_sync(0xffffffffu, rs, o);
                bsum[r] += rs;
            }
            // write P
#pragma unroll
            for (int r = 0; r < 4; r++) {
                const int row = 2 * ty + (r & 1) + 32 * (r >> 1);
                *reinterpret_cast<float2*>(&sm.Ps[row][2 * tx]) = make_float2(sfr[r][0], sfr[r][1]);
                *reinterpret_cast<float2*>(&sm.Ps[row][2 * tx + 32]) = make_float2(sfr[r][2], sfr[r][3]);
            }
            __syncthreads();

            // ---- GEMM2: acc += P V  (4x8 micro-tile) ----
#pragma unroll 4
            for (int jj = 0; jj < BN; jj++) {
                float pf[4];
#pragma unroll
                for (int r = 0; r < 4; r++) pf[r] = sm.Ps[2 * ty + (r & 1) + 32 * (r >> 1)][jj];
                const float2 v0 = *reinterpret_cast<const float2*>(&sm.Vs[jj][2 * tx]);
                const float2 v1 = *reinterpret_cast<const float2*>(&sm.Vs[jj][2 * tx + 32]);
                const float2 v2 = *reinterpret_cast<const float2*>(&sm.Vs[jj][2 * tx + 64]);
                const float2 v3 = *reinterpret_cast<const float2*>(&sm.Vs[jj][2 * tx + 96]);
                const float vf[8] = {v0.x, v0.y, v1.x, v1.y, v2.x, v2.y, v3.x, v3.y};
#pragma unroll
                for (int r = 0; r < 4; r++)
#pragma unroll
                    for (int c = 0; c < 8; c++) acc[r][c] += pf[r] * vf[c];
            }
        }

        // ---- epilogue: divide by max(|b|, floor)+1e-6 and store ----
        if (tx == 0) {
#pragma unroll
            for (int r = 0; r < 4; r++) sm.bs[2 * ty + (r & 1) + 32 * (r >> 1)] = bsum[r];
        }
        __syncthreads();
#pragma unroll
        for (int r = 0; r < 4; r++) {
            const int row = 2 * ty + (r & 1) + 32 * (r >> 1);
            const float nv = fmaxf(fabsf(sm.bs[row]), sm.nfl[row]) + 1e-6f;
            const float inv = 1.0f / nv;
            float* orow = out + (size_t)(i0 + row) * DIM + h * HD;
#pragma unroll
            for (int g = 0; g < 4; g++) {
                *reinterpret_cast<float2*>(orow + 2 * tx + 32 * g) =
                    make_float2(acc[r][2 * g] * inv, acc[r][2 * g + 1] * inv);
            }
        }
        __syncthreads();  // sm.bs/M2/nfl reads done before next half re-stages
    }
}

// ---------------- kernel D: GroupNorm over each (token, head) ----------------
__global__ void gn_kernel(float* __restrict__ out, const float* __restrict__ gn_w,
                          const float* __restrict__ gn_b) {
    const int s = blockIdx.x;
    const int h = threadIdx.x >> 5;
    const int lane = threadIdx.x & 31;
    float* row = out + (size_t)s * DIM + h * HD;

    float4 x = *reinterpret_cast<const float4*>(row + lane * 4);
    float sum = x.x + x.y + x.z + x.w;
#pragma unroll
    for (int o = 16; o; o >>= 1) sum += __shfl_xor_sync(0xffffffffu, sum, o);
    const float mean = sum * (1.0f / 128.0f);

    const float d0 = x.x - mean, d1 = x.y - mean, d2 = x.z - mean, d3 = x.w - mean;
    float sq = d0 * d0 + d1 * d1 + d2 * d2 + d3 * d3;
#pragma unroll
    for (int o = 16; o; o >>= 1) sq += __shfl_xor_sync(0xffffffffu, sq, o);
    const float inv = rsqrtf(sq * (1.0f / 128.0f) + 1e-5f);

    const float4 w = *reinterpret_cast<const float4*>(gn_w + h * HD + lane * 4);
    const float4 b = *reinterpret_cast<const float4*>(gn_b + h * HD + lane * 4);
    x.x = d0 * inv * w.x + b.x;
    x.y = d1 * inv * w.y + b.y;
    x.z = d2 * inv * w.z + b.z;
    x.w = d3 * inv * w.w + b.w;
    *reinterpret_cast<float4*>(row + lane * 4) = x;
}

// ---------------- launch ----------------
extern "C" void kernel_launch(void* const* d_in, const int* in_sizes, int n_in,
                              void* d_out, int out_size) {
    const float* q = (const float*)d_in[0];
    const float* k = (const float*)d_in[1];
    const float* v = (const float*)d_in[2];
    const float* Wi_w = (const float*)d_in[3];
    const float* Wi_b = (const float*)d_in[4];
    const float* Wf_w = (const float*)d_in[5];
    const float* Wf_b = (const float*)d_in[6];
    const float* gn_w = (const float*)d_in[7];
    const float* gn_b = (const float*)d_in[8];
    float* out = (float*)d_out;

    gates_kernel<<<SEQ, 256>>>(q, k, v, Wi_w, Wi_b, Wf_w, Wf_b);
    scan_kernel<<<NHEADS, 256>>>();

    const int smem_bytes = (int)sizeof(SmemC);
    cudaFuncSetAttribute(mlstm_main, cudaFuncAttributeMaxDynamicSharedMemorySize, smem_bytes);
    dim3 grid(16, NHEADS);
    mlstm_main<<<grid, 256, smem_bytes>>>(q, k, v, out);

    gn_kernel<<<SEQ, 256>>>(out, gn_w, gn_b);
}

// round 3
// speedup vs baseline: 2.6219x; 2.6219x over previous
#include <cuda_runtime.h>
#include <cuda_bf16.h>
#include <cstdint>
#include <math.h>

#define SEQ 2048
#define DIM 1024
#define NHEADS 8
#define HD 128
#define LOG2E 1.4426950408889634f
#define INV_TAU 0.088388347648318447f

// ---------------- scratch (device globals; no allocation) ----------------
__device__ float g_itilde[NHEADS * SEQ];
__device__ float g_logsig[NHEADS * SEQ];
__device__ float g_a2[NHEADS * SEQ];      // a_j * log2(e)
__device__ float g_M2[NHEADS * SEQ];      // M_i * log2(e)
__device__ float g_nfloor[NHEADS * SEQ];  // exp(-(csum_i + M_i))
__device__ float g_Opart[2][SEQ * DIM];   // partial O per column-parity
__device__ float g_bpart[2][NHEADS * SEQ];

// ---------------- smem layout (bytes). Row pitch = 136 bf16 = 272 B ----------------
#define PITCH 272
#define OFF_QHI 0          /* 128 x 136 bf16 = 34816 */
#define OFF_QLO 34816
#define OFF_KHI 69632      /* 64 x 136 bf16 = 17408 */
#define OFF_KLO 87040
#define OFF_VHI 104448
#define OFF_VLO 121856
#define OFF_EA 139264      /* 68 floats */
#define EAF (OFF_EA / 4)
#define SMEM_TOTAL (OFF_EA + 272)

// ---------------- helpers ----------------
__device__ __forceinline__ uint32_t smem_u32(const void* p) {
    uint32_t a;
    asm("{ .reg .u64 t; cvta.to.shared.u64 t, %1; cvt.u32.u64 %0, t; }" : "=r"(a) : "l"(p));
    return a;
}
__device__ __forceinline__ void ldsm4(uint32_t* r, uint32_t addr) {
    asm volatile("ldmatrix.sync.aligned.m8n8.x4.shared.b16 {%0,%1,%2,%3}, [%4];"
                 : "=r"(r[0]), "=r"(r[1]), "=r"(r[2]), "=r"(r[3]) : "r"(addr));
}
__device__ __forceinline__ void ldsm4t(uint32_t* r, uint32_t addr) {
    asm volatile("ldmatrix.sync.aligned.m8n8.x4.trans.shared.b16 {%0,%1,%2,%3}, [%4];"
                 : "=r"(r[0]), "=r"(r[1]), "=r"(r[2]), "=r"(r[3]) : "r"(addr));
}
__device__ __forceinline__ void mma16816(float* d, const uint32_t* a, const uint32_t* b) {
    asm volatile(
        "mma.sync.aligned.m16n8k16.row.col.f32.bf16.bf16.f32 "
        "{%0,%1,%2,%3}, {%4,%5,%6,%7}, {%8,%9}, {%0,%1,%2,%3};"
        : "+f"(d[0]), "+f"(d[1]), "+f"(d[2]), "+f"(d[3])
        : "r"(a[0]), "r"(a[1]), "r"(a[2]), "r"(a[3]), "r"(b[0]), "r"(b[1]));
}
__device__ __forceinline__ uint32_t pack_bf2(float a, float b) {
    __nv_bfloat162 t = __floats2bfloat162_rn(a, b);
    return *reinterpret_cast<uint32_t*>(&t);
}
__device__ __forceinline__ float bf_hi(float f) {
    return __bfloat162float(__float2bfloat16(f));
}

// ---------------- kernel A: gate projections (verified R1) ----------------
__global__ void gates_kernel(const float* __restrict__ q, const float* __restrict__ k,
                             const float* __restrict__ v,
                             const float* __restrict__ Wi_w, const float* __restrict__ Wi_b,
                             const float* __restrict__ Wf_w, const float* __restrict__ Wf_b) {
    const int s = blockIdx.x;
    const int h = threadIdx.x >> 5;
    const int lane = threadIdx.x & 31;
    const float* wi = Wi_w + h * 3 * DIM;
    const float* wf = Wf_w + h * 3 * DIM;
    const float* qr = q + (size_t)s * DIM;
    const float* kr = k + (size_t)s * DIM;
    const float* vr = v + (size_t)s * DIM;

    float si = 0.f, sf = 0.f;
#pragma unroll
    for (int m = 0; m < 8; m++) {
        const int d = m * 128 + lane * 4;
        const float4 xq = *reinterpret_cast<const float4*>(qr + d);
        const float4 xk = *reinterpret_cast<const float4*>(kr + d);
        const float4 xv = *reinterpret_cast<const float4*>(vr + d);
        float4 w0 = *reinterpret_cast<const float4*>(wi + d);
        float4 w1 = *reinterpret_cast<const float4*>(wi + DIM + d);
        float4 w2 = *reinterpret_cast<const float4*>(wi + 2 * DIM + d);
        si += xq.x * w0.x + xq.y * w0.y + xq.z * w0.z + xq.w * w0.w;
        si += xk.x * w1.x + xk.y * w1.y + xk.z * w1.z + xk.w * w1.w;
        si += xv.x * w2.x + xv.y * w2.y + xv.z * w2.z + xv.w * w2.w;
        w0 = *reinterpret_cast<const float4*>(wf + d);
        w1 = *reinterpret_cast<const float4*>(wf + DIM + d);
        w2 = *reinterpret_cast<const float4*>(wf + 2 * DIM + d);
        sf += xq.x * w0.x + xq.y * w0.y + xq.z * w0.z + xq.w * w0.w;
        sf += xk.x * w1.x + xk.y * w1.y + xk.z * w1.z + xk.w * w1.w;
        sf += xv.x * w2.x + xv.y * w2.y + xv.z * w2.z + xv.w * w2.w;
    }
#pragma unroll
    for (int o = 16; o; o >>= 1) {
        si += __shfl_xor_sync(0xffffffffu, si, o);
        sf += __shfl_xor_sync(0xffffffffu, sf, o);
    }
    if (lane == 0) {
        g_itilde[h * SEQ + s] = si + Wi_b[h];
        const float ft = sf + Wf_b[h];
        g_logsig[h * SEQ + s] = fminf(ft, 0.f) - log1pf(__expf(-fabsf(ft)));
    }
}

// ---------------- kernel B: per-head scans (verified R1) ----------------
__global__ void scan_kernel() {
    const int h = blockIdx.x;
    const int t = threadIdx.x;
    __shared__ float sc[256];

    float cs[8];
    float run = 0.f;
#pragma unroll
    for (int m = 0; m < 8; m++) {
        run += g_logsig[h * SEQ + t * 8 + m];
        cs[m] = run;
    }
    sc[t] = run;
    __syncthreads();
#pragma unroll
    for (int off = 1; off < 256; off <<= 1) {
        const float vv = sc[t];
        const float uu = (t >= off) ? sc[t - off] : 0.f;
        __syncthreads();
        sc[t] = vv + uu;
        __syncthreads();
    }
    const float base = (t == 0) ? 0.f : sc[t - 1];

    float a[8], amax[8], csum[8];
    float runm = -3.402823466e38f;
#pragma unroll
    for (int m = 0; m < 8; m++) {
        csum[m] = base + cs[m];
        a[m] = g_itilde[h * SEQ + t * 8 + m] - csum[m];
        runm = fmaxf(runm, a[m]);
        amax[m] = runm;
    }
    __syncthreads();
    sc[t] = runm;
    __syncthreads();
#pragma unroll
    for (int off = 1; off < 256; off <<= 1) {
        const float vv = sc[t];
        const float uu = (t >= off) ? sc[t - off] : -3.402823466e38f;
        __syncthreads();
        sc[t] = fmaxf(vv, uu);
        __syncthreads();
    }
    const float mbase = (t == 0) ? -3.402823466e38f : sc[t - 1];

#pragma unroll
    for (int m = 0; m < 8; m++) {
        const int j = h * SEQ + t * 8 + m;
        const float Mv = fmaxf(mbase, amax[m]);
        g_a2[j] = a[m] * LOG2E;
        g_M2[j] = Mv * LOG2E;
        g_nfloor[j] = exp2f(-(csum[m] + Mv) * LOG2E);
    }
}

// ---------------- main kernel: HMMA flash mLSTM ----------------
// grid (16, 8): blockIdx.x = pair p (>>1) + column parity (&1); blockIdx.y = head.
// CTA handles row-tiles {p, 15-p} (128 rows each) over columns ct with ct%2==par.
// Each CTA does exactly 17 col-tiles -> perfect balance, 128 CTAs = one wave.
__global__ void __launch_bounds__(256, 1)
mlstm_mma(const float* __restrict__ q, const float* __restrict__ k,
          const float* __restrict__ v) {
    extern __shared__ char smraw[];
    const uint32_t sb = smem_u32(smraw);
    float* smf = reinterpret_cast<float*>(smraw);

    const int tid = threadIdx.x;
    const int lane = tid & 31;
    const int warp = tid >> 5;
    const int qr = lane >> 2;  // quad row
    const int qc = lane & 3;   // quad col
    const int h = blockIdx.y, hb = h * SEQ;
    const int p = blockIdx.x >> 1, par = blockIdx.x & 1;
    const int m0 = warp * 16;

    // per-lane ldmatrix offsets (bytes within each tile buffer)
    const uint32_t offA = (uint32_t)(m0 + (lane & 15)) * PITCH + ((lane >> 4) * 8) * 2;
    const uint32_t offB = (uint32_t)(((lane >> 4) & 1) * 8 + (lane & 7)) * PITCH +
                          (((lane >> 3) & 1) * 8) * 2;
    const uint32_t offV = (uint32_t)(lane & 15) * PITCH + ((lane >> 4) * 8) * 2;

    for (int hs = 0; hs < 2; hs++) {
        const int rtc = hs ? (15 - p) : p;
        const int i0 = rtc * 128;
        __syncthreads();  // previous half finished reading Q

        // --- stage Q hi/lo (scaled by 1/tau) ---
        for (int idx = tid; idx < 128 * 32; idx += 256) {
            const int r = idx >> 5, c4 = (idx & 31) * 4;
            float4 f = *reinterpret_cast<const float4*>(q + (size_t)(i0 + r) * DIM + h * HD + c4);
            f.x *= INV_TAU; f.y *= INV_TAU; f.z *= INV_TAU; f.w *= INV_TAU;
            const float hx = bf_hi(f.x), hy = bf_hi(f.y), hz = bf_hi(f.z), hw = bf_hi(f.w);
            char* bp = smraw + OFF_QHI + r * PITCH + c4 * 2;
            *reinterpret_cast<uint32_t*>(bp) = pack_bf2(hx, hy);
            *reinterpret_cast<uint32_t*>(bp + 4) = pack_bf2(hz, hw);
            char* lp = bp + (OFF_QLO - OFF_QHI);
            *reinterpret_cast<uint32_t*>(lp) = pack_bf2(f.x - hx, f.y - hy);
            *reinterpret_cast<uint32_t*>(lp + 4) = pack_bf2(f.z - hz, f.w - hw);
        }

        const int r_lo = i0 + m0 + qr;
        const int r_hi = r_lo + 8;
        const float m2_lo = g_M2[hb + r_lo];
        const float m2_hi = g_M2[hb + r_hi];

        float accO[16][4];
#pragma unroll
        for (int a = 0; a < 16; a++)
#pragma unroll
            for (int b = 0; b < 4; b++) accO[a][b] = 0.f;
        float bsl = 0.f, bsh = 0.f;

        const int n_ct = 2 * rtc + 2;
        for (int ct = par; ct < n_ct; ct += 2) {
            const int j0 = ct * 64;
            __syncthreads();  // previous tile done reading K/V

            // --- stage K and V hi/lo ---
            for (int idx = tid; idx < 64 * 32; idx += 256) {
                const int r = idx >> 5, c4 = (idx & 31) * 4;
                const float4 f = *reinterpret_cast<const float4*>(k + (size_t)(j0 + r) * DIM + h * HD + c4);
                const float hx = bf_hi(f.x), hy = bf_hi(f.y), hz = bf_hi(f.z), hw = bf_hi(f.w);
                char* bp = smraw + OFF_KHI + r * PITCH + c4 * 2;
                *reinterpret_cast<uint32_t*>(bp) = pack_bf2(hx, hy);
                *reinterpret_cast<uint32_t*>(bp + 4) = pack_bf2(hz, hw);
                char* lp = bp + (OFF_KLO - OFF_KHI);
                *reinterpret_cast<uint32_t*>(lp) = pack_bf2(f.x - hx, f.y - hy);
                *reinterpret_cast<uint32_t*>(lp + 4) = pack_bf2(f.z - hz, f.w - hw);

                const float4 g = *reinterpret_cast<const float4*>(v + (size_t)(j0 + r) * DIM + h * HD + c4);
                const float gx = bf_hi(g.x), gy = bf_hi(g.y), gz = bf_hi(g.z), gw = bf_hi(g.w);
                char* vp = smraw + OFF_VHI + r * PITCH + c4 * 2;
                *reinterpret_cast<uint32_t*>(vp) = pack_bf2(gx, gy);
                *reinterpret_cast<uint32_t*>(vp + 4) = pack_bf2(gz, gw);
                char* wp = vp + (OFF_VLO - OFF_VHI);
                *reinterpret_cast<uint32_t*>(wp) = pack_bf2(g.x - gx, g.y - gy);
                *reinterpret_cast<uint32_t*>(wp + 4) = pack_bf2(g.z - gz, g.w - gw);
            }
            if (tid < 64) smf[EAF + tid] = exp2f(g_a2[hb + j0 + tid] - g_M2[hb + j0 + 63]);
            if (tid == 64) smf[EAF + 64] = g_M2[hb + j0 + 63];
            __syncthreads();

            // fully-masked warp-tiles: last (odd) col-tile, rows < j0
            const bool fskip = (ct == 2 * rtc + 1) && (warp < 4);
            if (fskip) continue;

            // --- GEMM1: S = Q K^T (3-pass bf16 split) ---
            float accS[8][4];
#pragma unroll
            for (int a = 0; a < 8; a++)
#pragma unroll
                for (int b = 0; b < 4; b++) accS[a][b] = 0.f;

#pragma unroll
            for (int kt = 0; kt < 8; kt++) {
                uint32_t ah[4], al[4];
                const uint32_t aaddr = sb + OFF_QHI + offA + kt * 32;
                ldsm4(ah, aaddr);
                ldsm4(al, aaddr + (OFF_QLO - OFF_QHI));
#pragma unroll
                for (int np = 0; np < 4; np++) {
                    const uint32_t baddr = sb + OFF_KHI + offB + np * (16 * PITCH) + kt * 32;
                    uint32_t bh4[4], bl4[4];
                    ldsm4(bh4, baddr);
                    mma16816(accS[2 * np], ah, bh4);
                    mma16816(accS[2 * np + 1], ah, bh4 + 2);
                    ldsm4(bl4, baddr + (OFF_KLO - OFF_KHI));
                    mma16816(accS[2 * np], ah, bl4);
                    mma16816(accS[2 * np + 1], ah, bl4 + 2);
                    mma16816(accS[2 * np], al, bh4);
                    mma16816(accS[2 * np + 1], al, bh4 + 2);
                }
            }

            // --- decay weights + causal mask + rowsum ---
            const float ref2 = smf[EAF + 64];
            const float em_lo = exp2f(ref2 - m2_lo);
            const float em_hi = exp2f(ref2 - m2_hi);
            const bool diag = (ct >= 2 * rtc);
#pragma unroll
            for (int nt = 0; nt < 8; nt++) {
                const int col0 = nt * 8 + 2 * qc;
                const float w0 = smf[EAF + col0], w1 = smf[EAF + col0 + 1];
                float* c = accS[nt];
                float p00 = c[0] * w0 * em_lo, p01 = c[1] * w1 * em_lo;
                float p10 = c[2] * w0 * em_hi, p11 = c[3] * w1 * em_hi;
                if (diag) {
                    const int jc = j0 + col0;
                    if (jc > r_lo) p00 = 0.f;
                    if (jc + 1 > r_lo) p01 = 0.f;
                    if (jc > r_hi) p10 = 0.f;
                    if (jc + 1 > r_hi) p11 = 0.f;
                }
                bsl += p00 + p01;
                bsh += p10 + p11;
                c[0] = p00; c[1] = p01; c[2] = p10; c[3] = p11;
            }

            // --- GEMM2: O += P V (P from registers, 3-pass bf16 split) ---
#pragma unroll
            for (int kt2 = 0; kt2 < 4; kt2++) {
                const float* s0 = accS[2 * kt2];
                const float* s1 = accS[2 * kt2 + 1];
                const float h00 = bf_hi(s0[0]), h01 = bf_hi(s0[1]);
                const float h02 = bf_hi(s0[2]), h03 = bf_hi(s0[3]);
                const float h10 = bf_hi(s1[0]), h11 = bf_hi(s1[1]);
                const float h12 = bf_hi(s1[2]), h13 = bf_hi(s1[3]);
                uint32_t ph[4], pl[4];
                ph[0] = pack_bf2(h00, h01);
                ph[1] = pack_bf2(h02, h03);
                ph[2] = pack_bf2(h10, h11);
                ph[3] = pack_bf2(h12, h13);
                pl[0] = pack_bf2(s0[0] - h00, s0[1] - h01);
                pl[1] = pack_bf2(s0[2] - h02, s0[3] - h03);
                pl[2] = pack_bf2(s1[0] - h10, s1[1] - h11);
                pl[3] = pack_bf2(s1[2] - h12, s1[3] - h13);
#pragma unroll
                for (int dp = 0; dp < 8; dp++) {
                    const uint32_t vaddr = sb + OFF_VHI + offV + kt2 * (16 * PITCH) + dp * 32;
                    uint32_t vh4[4], vl4[4];
                    ldsm4t(vh4, vaddr);
                    mma16816(accO[2 * dp], ph, vh4);
                    mma16816(accO[2 * dp + 1], ph, vh4 + 2);
                    ldsm4t(vl4, vaddr + (OFF_VLO - OFF_VHI));
                    mma16816(accO[2 * dp], ph, vl4);
                    mma16816(accO[2 * dp + 1], ph, vl4 + 2);
                    mma16816(accO[2 * dp], pl, vh4);
                    mma16816(accO[2 * dp + 1], pl, vh4 + 2);
                }
            }
        }

        // --- reduce rowsums across quad, store partials ---
        bsl += __shfl_xor_sync(0xffffffffu, bsl, 1);
        bsl += __shfl_xor_sync(0xffffffffu, bsl, 2);
        bsh += __shfl_xor_sync(0xffffffffu, bsh, 1);
        bsh += __shfl_xor_sync(0xffffffffu, bsh, 2);
        if (qc == 0) {
            g_bpart[par][hb + r_lo] = bsl;
            g_bpart[par][hb + r_hi] = bsh;
        }
        float* od = g_Opart[par];
#pragma unroll
        for (int dt = 0; dt < 16; dt++) {
            const int col = h * HD + dt * 8 + 2 * qc;
            *reinterpret_cast<float2*>(od + (size_t)r_lo * DIM + col) =
                make_float2(accO[dt][0], accO[dt][1]);
            *reinterpret_cast<float2*>(od + (size_t)r_hi * DIM + col) =
                make_float2(accO[dt][2], accO[dt][3]);
        }
    }
}

// ---------------- merge + denominator + GroupNorm ----------------
__global__ void merge_gn(float* __restrict__ out, const float* __restrict__ gn_w,
                         const float* __restrict__ gn_b) {
    const int s = blockIdx.x;
    const int h = threadIdx.x >> 5;
    const int lane = threadIdx.x & 31;
    const size_t off = (size_t)s * DIM + h * HD + lane * 4;

    const float4 a = *reinterpret_cast<const float4*>(g_Opart[0] + off);
    const float4 b4 = *reinterpret_cast<const float4*>(g_Opart[1] + off);
    const float bs = g_bpart[0][h * SEQ + s] + g_bpart[1][h * SEQ + s];
    const float inv = 1.0f / (fmaxf(fabsf(bs), g_nfloor[h * SEQ + s]) + 1e-6f);

    float4 x;
    x.x = (a.x + b4.x) * inv;
    x.y = (a.y + b4.y) * inv;
    x.z = (a.z + b4.z) * inv;
    x.w = (a.w + b4.w) * inv;

    float sum = x.x + x.y + x.z + x.w;
#pragma unroll
    for (int o = 16; o; o >>= 1) sum += __shfl_xor_sync(0xffffffffu, sum, o);
    const float mean = sum * (1.0f / 128.0f);
    const float d0 = x.x - mean, d1 = x.y - mean, d2 = x.z - mean, d3 = x.w - mean;
    float sq = d0 * d0 + d1 * d1 + d2 * d2 + d3 * d3;
#pragma unroll
    for (int o = 16; o; o >>= 1) sq += __shfl_xor_sync(0xffffffffu, sq, o);
    const float istd = rsqrtf(sq * (1.0f / 128.0f) + 1e-5f);

    const float4 w = *reinterpret_cast<const float4*>(gn_w + h * HD + lane * 4);
    const float4 bb = *reinterpret_cast<const float4*>(gn_b + h * HD + lane * 4);
    float4 y;
    y.x = d0 * istd * w.x + bb.x;
    y.y = d1 * istd * w.y + bb.y;
    y.z = d2 * istd * w.z + bb.z;
    y.w = d3 * istd * w.w + bb.w;
    *reinterpret_cast<float4*>(out + off) = y;
}

// ---------------- launch ----------------
extern "C" void kernel_launch(void* const* d_in, const int* in_sizes, int n_in,
                              void* d_out, int out_size) {
    const float* q = (const float*)d_in[0];
    const float* k = (const float*)d_in[1];
    const float* v = (const float*)d_in[2];
    const float* Wi_w = (const float*)d_in[3];
    const float* Wi_b = (const float*)d_in[4];
    const float* Wf_w = (const float*)d_in[5];
    const float* Wf_b = (const float*)d_in[6];
    const float* gn_w = (const float*)d_in[7];
    const float* gn_b = (const float*)d_in[8];
    float* out = (float*)d_out;

    gates_kernel<<<SEQ, 256>>>(q, k, v, Wi_w, Wi_b, Wf_w, Wf_b);
    scan_kernel<<<NHEADS, 256>>>();

    cudaFuncSetAttribute(mlstm_mma, cudaFuncAttributeMaxDynamicSharedMemorySize, SMEM_TOTAL);
    dim3 grid(16, NHEADS);
    mlstm_mma<<<grid, 256, SMEM_TOTAL>>>(q, k, v);

    merge_gn<<<SEQ, 256>>>(out, gn_w, gn_b);
}